// round 14
// baseline (speedup 1.0000x reference)
#include <cuda_runtime.h>
#include <cuda_fp16.h>
#include <math.h>
#include <cstdint>

// Problem constants
#define BB 2
#define SS 1024
#define DD 768
#define HH 12
#define HD 64
#define DFF 3072
#define TD 2304           // 3*D
#define MROWS (BB*SS)     // 2048

// weight scratch offsets (halfs)
#define W_QKV_OFF 0
#define W_O_OFF   (TD * DD)
#define W_W1_OFF  (W_O_OFF + DD * DD)
#define W_W2_OFF  (W_W1_OFF + DFF * DD)
#define W_TOTAL   (W_W2_OFF + DD * DFF)

// ---------------- scratch (__device__ globals; no allocation) ----------------
__device__ __half g_hxln[MROWS * DD];
__device__ __half g_hqkv[MROWS * TD];
__device__ __half g_hattn[MROWS * DD];
__device__ __half g_hh1[MROWS * DFF];
__device__ __half g_hw[W_TOTAL];
__device__ float  g_res1[MROWS * DD];
__device__ unsigned char g_relpack[BB * SS * SS];

// ================= helpers =================
__device__ __forceinline__ uint32_t smem_to_u32(const void* p) {
    uint32_t a;
    asm("{ .reg .u64 t; cvta.to.shared.u64 t, %1; cvt.u32.u64 %0, t; }" : "=r"(a) : "l"(p));
    return a;
}
__device__ __forceinline__ void cp16(uint32_t saddr, const void* gaddr) {
    asm volatile("cp.async.cg.shared.global [%0], [%1], 16;" :: "r"(saddr), "l"(gaddr) : "memory");
}
#define CP_COMMIT() asm volatile("cp.async.commit_group;" ::: "memory")
#define CP_WAIT(n)  asm volatile("cp.async.wait_group %0;" :: "n"(n) : "memory")

__device__ __forceinline__ void ldsm4(uint32_t* r, uint32_t a) {
    asm volatile("ldmatrix.sync.aligned.m8n8.x4.shared.b16 {%0,%1,%2,%3}, [%4];"
        : "=r"(r[0]), "=r"(r[1]), "=r"(r[2]), "=r"(r[3]) : "r"(a));
}
__device__ __forceinline__ void ldsm4t(uint32_t* r, uint32_t a) {
    asm volatile("ldmatrix.sync.aligned.m8n8.x4.trans.shared.b16 {%0,%1,%2,%3}, [%4];"
        : "=r"(r[0]), "=r"(r[1]), "=r"(r[2]), "=r"(r[3]) : "r"(a));
}
// D(16x8) += A(16x16) * B(16x8), f16 in, f32 accum
__device__ __forceinline__ void mma16(float* c, const uint32_t* a, const uint32_t* b) {
    asm volatile("mma.sync.aligned.m16n8k16.row.col.f32.f16.f16.f32 "
        "{%0,%1,%2,%3}, {%4,%5,%6,%7}, {%8,%9}, {%0,%1,%2,%3};"
        : "+f"(c[0]), "+f"(c[1]), "+f"(c[2]), "+f"(c[3])
        : "r"(a[0]), "r"(a[1]), "r"(a[2]), "r"(a[3]), "r"(b[0]), "r"(b[1]));
}
__device__ __forceinline__ uint32_t packh2(float a, float b) {
    __half2 h = __floats2half2_rn(a, b);
    return *(uint32_t*)&h;
}

// ================= f16 mma GEMM (unchanged from R12) ================
template<int MT>
__global__ void __launch_bounds__(256) gemm_h_kernel(
    const __half* __restrict__ A, const __half* __restrict__ B,
    const float* __restrict__ bias, const float* __restrict__ resid,
    float* __restrict__ Cf, __half* __restrict__ Ch,
    int N, int K, int do_relu)
{
    constexpr int BM = MT * 32;
    constexpr int STAGE = (BM + 128) * 144;
    extern __shared__ char smem[];
    uint32_t sb = smem_to_u32(smem);
    int tid = threadIdx.x;
    int warp = tid >> 5, lane = tid & 31;
    int g = lane >> 2, t = lane & 3;
    int q8 = lane >> 3, r8 = lane & 7;
    int wm = warp >> 2, wn = warp & 3;
    int row0 = blockIdx.y * BM, col0 = blockIdx.x * 128;
    int ktiles = K >> 6;

    const __half* gA = A + (size_t)row0 * K;
    const __half* gB = B + (size_t)col0 * K;

    float acc[MT][4][4];
    #pragma unroll
    for (int i = 0; i < MT; i++)
        #pragma unroll
        for (int j = 0; j < 4; j++)
            #pragma unroll
            for (int e = 0; e < 4; e++) acc[i][j][e] = 0.0f;

    auto load_tile = [&](int kt, int buf) {
        uint32_t s0 = sb + buf * STAGE;
        const __half* a = gA + kt * 64;
        const __half* b = gB + kt * 64;
        #pragma unroll
        for (int j = 0; j < MT; j++) {
            int e = tid + j * 256;
            int r = e >> 3, c = e & 7;
            cp16(s0 + (uint32_t)(r * 144 + c * 16), a + (size_t)r * K + c * 8);
        }
        uint32_t sB0 = s0 + (uint32_t)BM * 144;
        #pragma unroll
        for (int j = 0; j < 4; j++) {
            int e = tid + j * 256;
            int r = e >> 3, c = e & 7;
            cp16(sB0 + (uint32_t)(r * 144 + c * 16), b + (size_t)r * K + c * 8);
        }
        CP_COMMIT();
    };

    load_tile(0, 0);

    uint32_t aOff = ((uint32_t)(wm * MT * 16 + (q8 & 1) * 8 + r8) * 72 + (q8 >> 1) * 8) * 2;
    uint32_t bOff = ((uint32_t)(wn * 32 + (q8 >> 1) * 8 + r8) * 72 + (q8 & 1) * 8) * 2;

    for (int kt = 0; kt < ktiles; kt++) {
        int buf = kt & 1;
        CP_WAIT(0);
        __syncthreads();
        if (kt + 1 < ktiles) load_tile(kt + 1, buf ^ 1);

        uint32_t sA = sb + buf * STAGE;
        uint32_t sB = sA + (uint32_t)BM * 144;

        #pragma unroll
        for (int ks = 0; ks < 4; ks++) {
            uint32_t af[MT][4];
            #pragma unroll
            for (int mt = 0; mt < MT; mt++)
                ldsm4(af[mt], sA + aOff + (uint32_t)(mt * 16 * 72 + ks * 16) * 2);
            uint32_t bf[4][2];
            #pragma unroll
            for (int np = 0; np < 2; np++) {
                uint32_t tmp[4];
                ldsm4(tmp, sB + bOff + (uint32_t)(np * 16 * 72 + ks * 16) * 2);
                bf[2*np][0] = tmp[0]; bf[2*np][1] = tmp[1];
                bf[2*np+1][0] = tmp[2]; bf[2*np+1][1] = tmp[3];
            }
            #pragma unroll
            for (int mt = 0; mt < MT; mt++)
                #pragma unroll
                for (int nt = 0; nt < 4; nt++)
                    mma16(acc[mt][nt], af[mt], bf[nt]);
        }
    }
    __syncthreads();

    float* eb = (float*)smem;
    #pragma unroll
    for (int mt = 0; mt < MT; mt++) {
        int r0 = wm * MT * 16 + mt * 16 + g;
        #pragma unroll
        for (int nt = 0; nt < 4; nt++) {
            int c0 = wn * 32 + nt * 8 + 2 * t;
            eb[r0 * 132 + c0]           = acc[mt][nt][0];
            eb[r0 * 132 + c0 + 1]       = acc[mt][nt][1];
            eb[(r0 + 8) * 132 + c0]     = acc[mt][nt][2];
            eb[(r0 + 8) * 132 + c0 + 1] = acc[mt][nt][3];
        }
    }
    __syncthreads();

    int c = tid & 127;
    int rs = tid >> 7;
    float bv = bias ? bias[col0 + c] : 0.0f;
    for (int r = rs; r < BM; r += 2) {
        float v = eb[r * 132 + c] + bv;
        size_t off = (size_t)(row0 + r) * N + col0 + c;
        if (resid) v += resid[off];
        if (do_relu) v = fmaxf(v, 0.0f);
        if (Ch) Ch[off] = __float2half(v);
        else    Cf[off] = v;
    }
}

#define GEMM_SMEM_128 73728
#define GEMM_SMEM_64  55296

// ---------------- LayerNorm: fp32 in, half out ----------------
__global__ void ln_kernel(const float* __restrict__ x,
                          const float* __restrict__ g,
                          const float* __restrict__ b,
                          __half* __restrict__ y)
{
    __shared__ float s1[256], s2[256];
    int row = blockIdx.x;
    const float* xr = x + (size_t)row * DD;
    __half* yr = y + (size_t)row * DD;
    int tid = threadIdx.x;

    float v0 = xr[tid], v1 = xr[tid + 256], v2 = xr[tid + 512];
    float sum = v0 + v1 + v2;
    float sq  = v0*v0 + v1*v1 + v2*v2;
    s1[tid] = sum; s2[tid] = sq;
    __syncthreads();
    for (int o = 128; o > 0; o >>= 1) {
        if (tid < o) { s1[tid] += s1[tid+o]; s2[tid] += s2[tid+o]; }
        __syncthreads();
    }
    float mean = s1[0] * (1.0f / DD);
    float var  = s2[0] * (1.0f / DD) - mean * mean;
    float inv  = rsqrtf(var + 1e-5f);
    yr[tid]       = __float2half((v0 - mean) * inv * g[tid]       + b[tid]);
    yr[tid + 256] = __float2half((v1 - mean) * inv * g[tid + 256] + b[tid + 256]);
    yr[tid + 512] = __float2half((v2 - mean) * inv * g[tid + 512] + b[tid + 512]);
}

// ---------------- prep ----------------
__global__ void pack_kernel(const int* __restrict__ relm, unsigned char* __restrict__ out, int n)
{
    int i = blockIdx.x * 256 + threadIdx.x;
    if (i < n) out[i] = (unsigned char)(relm[i] + 1);
}

__global__ void h_convert_kernel(const float4* __restrict__ s0, int n0,
                                 const float4* __restrict__ s1, int n1,
                                 const float4* __restrict__ s2, int n2,
                                 const float4* __restrict__ s3, int n3,
                                 __half2* __restrict__ dst)
{
    int i = blockIdx.x * 256 + threadIdx.x;
    const float4* s;
    int j = i;
    if (j < n0) s = s0;
    else { j -= n0;
        if (j < n1) { s = s1; }
        else { j -= n1;
            if (j < n2) { s = s2; }
            else { j -= n2; if (j >= n3) return; s = s3; }
        }
    }
    float4 v = s[j];
    dst[2*i]   = __floats2half2_rn(v.x, v.y);
    dst[2*i+1] = __floats2half2_rn(v.z, v.w);
}

// ================= FA2-style fp16 flash attention =================
// CTA: 128 queries x head x batch. 256 threads = 8 warps, each warp = 16 whole
// query rows vs ALL 64 keys -> softmax entirely in registers (shfl over t-lanes).
// P stays in registers: S-accum fragments repack directly into PV A-fragments.
#define KHB 144                    // bytes per K/V smem row (72 halfs)
#define SK_OFF 0                   // K double buffer: 2 x 64 x 144 = 18432 (Q staging overlays)
#define SV_OFF 18432               // V double buffer: 18432
#define RR_OFF 36864               // rel projections: 128*3 floats = 1536
#define FATTN_SMEM (RR_OFF + 1536) // 38400

__global__ void __launch_bounds__(256, 2) flash_attn_kernel(
    const __half* __restrict__ qkv,
    const unsigned char* __restrict__ relpack,
    const unsigned char* __restrict__ mask,
    const float* __restrict__ relA,
    __half* __restrict__ out)
{
    extern __shared__ char smem[];
    uint32_t sb = smem_to_u32(smem);
    __half* Qs = (__half*)(smem + SK_OFF);      // Q staging (overlays K buffers)
    float* rr  = (float*)(smem + RR_OFF);

    int tid = threadIdx.x;
    int warp = tid >> 5, lane = tid & 31;
    int g = lane >> 2, t = lane & 3;
    int q8 = lane >> 3, r8 = lane & 7;
    int q0 = blockIdx.x * 128;
    int h  = blockIdx.y;
    int b  = blockIdx.z;
    const __half* base = qkv + (size_t)b * SS * TD;
    const unsigned char* relrow = relpack + ((size_t)b * SS + q0) * SS;
    const unsigned char* maskp = mask + b * SS;

    // stage Q*0.125 [128 x 64] into smem (72-half rows)
    for (int i = tid; i < 128 * 32; i += 256) {
        int q = i >> 5, d2 = i & 31;
        __half2 v = *(const __half2*)(base + (size_t)(q0 + q) * TD + h * HD + d2 * 2);
        float2 f = __half22float2(v);
        *(__half2*)(Qs + q * 72 + d2 * 2) = __floats2half2_rn(f.x * 0.125f, f.y * 0.125f);
    }
    __syncthreads();

    // rel projections rr[q][c] (scale folded via scaled Q)
    for (int i = tid; i < 128 * 3; i += 256) {
        int q = i / 3, c = i % 3;
        float s = 0.0f;
        #pragma unroll
        for (int d = 0; d < HD; d++) s += __half2float(Qs[q * 72 + d]) * relA[c * HD + d];
        rr[i] = s;
    }
    __syncthreads();

    // Q fragments: warp's 16 rows, 4 k-chunks
    uint32_t qf[4][4];
    {
        uint32_t qOff = sb + SK_OFF +
            ((uint32_t)(warp * 16 + (q8 & 1) * 8 + r8) * 72 + (q8 >> 1) * 8) * 2;
        #pragma unroll
        for (int ks = 0; ks < 4; ks++)
            ldsm4(qf[ks], qOff + (uint32_t)(ks * 16) * 2);
    }
    __syncthreads();   // Q staging area free for K tiles

    // K+V loader: 64 rows x 64 halfs each
    auto load_tile = [&](int kt, int buf) {
        uint32_t sK = sb + SK_OFF + buf * 64 * KHB;
        uint32_t sV = sb + SV_OFF + buf * 64 * KHB;
        const __half* srcK = base + (size_t)kt * 64 * TD + DD + h * HD;
        const __half* srcV = base + (size_t)kt * 64 * TD + 2 * DD + h * HD;
        #pragma unroll
        for (int j = 0; j < 2; j++) {
            int e = tid + j * 256;
            int r = e >> 3, c = e & 7;
            cp16(sK + (uint32_t)(r * KHB + c * 16), srcK + (size_t)r * TD + c * 8);
            cp16(sV + (uint32_t)(r * KHB + c * 16), srcV + (size_t)r * TD + c * 8);
        }
        CP_COMMIT();
    };

    float oacc[8][4];
    #pragma unroll
    for (int nt = 0; nt < 8; nt++)
        #pragma unroll
        for (int e = 0; e < 4; e++) oacc[nt][e] = 0.0f;
    float m0 = -1e30f, m1 = -1e30f, l0 = 0.0f, l1 = 0.0f;

    load_tile(0, 0);

    // per-thread ldmatrix offsets
    uint32_t kOff = ((uint32_t)((q8 >> 1) * 8 + r8) * 72 + (q8 & 1) * 8) * 2;   // K (keys x d)
    uint32_t vOff = ((uint32_t)((q8 & 1) * 8 + r8) * 72 + (q8 >> 1) * 8) * 2;   // V (trans)
    int qr0 = warp * 16 + g;            // this thread's first query row
    const unsigned char* rp0 = relrow + (size_t)qr0 * SS + 2 * t;
    const unsigned char* rp1 = rp0 + 8 * SS;

    for (int kt = 0; kt < 16; kt++) {
        int buf = kt & 1;
        CP_WAIT(0);
        __syncthreads();
        if (kt + 1 < 16) load_tile(kt + 1, buf ^ 1);

        // prefetch rel idx (u16 = 2 adjacent keys) + mask
        uint32_t ix0[8], ix1[8], mk[8];
        #pragma unroll
        for (int nt = 0; nt < 8; nt++) {
            int ko = kt * 64 + nt * 8;
            ix0[nt] = *(const unsigned short*)(rp0 + ko);
            ix1[nt] = *(const unsigned short*)(rp1 + ko);
            mk[nt]  = *(const unsigned short*)(maskp + ko + 2 * t);
        }

        // S = Qs K^T : warp 16 rows x 64 keys
        float sacc[8][4];
        #pragma unroll
        for (int nt = 0; nt < 8; nt++)
            #pragma unroll
            for (int e = 0; e < 4; e++) sacc[nt][e] = 0.0f;
        uint32_t sK = sb + SK_OFF + buf * 64 * KHB;
        #pragma unroll
        for (int ks = 0; ks < 4; ks++) {
            #pragma unroll
            for (int np = 0; np < 4; np++) {
                uint32_t tmp[4];
                ldsm4(tmp, sK + kOff + (uint32_t)(np * 16 * 72 + ks * 16) * 2);
                uint32_t bfa[2] = {tmp[0], tmp[1]};
                uint32_t bfb[2] = {tmp[2], tmp[3]};
                mma16(sacc[2*np],     qf[ks], bfa);
                mma16(sacc[2*np + 1], qf[ks], bfb);
            }
        }

        // epilogue: +rel, mask; register softmax (reduce over t lanes only)
        float rm0 = -1e30f, rm1 = -1e30f;
        #pragma unroll
        for (int nt = 0; nt < 8; nt++) {
            float s0 = sacc[nt][0] + rr[qr0 * 3 + (ix0[nt] & 0xff)];
            float s1 = sacc[nt][1] + rr[qr0 * 3 + (ix0[nt] >> 8)];
            float s2 = sacc[nt][2] + rr[(qr0 + 8) * 3 + (ix1[nt] & 0xff)];
            float s3 = sacc[nt][3] + rr[(qr0 + 8) * 3 + (ix1[nt] >> 8)];
            if (mk[nt] & 0xffu)  { s0 = -1e30f; s2 = -1e30f; }
            if (mk[nt] & 0xff00u){ s1 = -1e30f; s3 = -1e30f; }
            sacc[nt][0] = s0; sacc[nt][1] = s1; sacc[nt][2] = s2; sacc[nt][3] = s3;
            rm0 = fmaxf(rm0, fmaxf(s0, s1));
            rm1 = fmaxf(rm1, fmaxf(s2, s3));
        }
        #pragma unroll
        for (int o = 1; o <= 2; o <<= 1) {
            rm0 = fmaxf(rm0, __shfl_xor_sync(0xffffffffu, rm0, o));
            rm1 = fmaxf(rm1, __shfl_xor_sync(0xffffffffu, rm1, o));
        }
        float mn0 = fmaxf(m0, rm0), mn1 = fmaxf(m1, rm1);
        float sc0 = __expf(m0 - mn0), sc1 = __expf(m1 - mn1);
        m0 = mn0; m1 = mn1;

        // P = exp(s - m) -> pack straight into PV A-fragments
        uint32_t af[4][4];
        float rs0 = 0.0f, rs1 = 0.0f;
        #pragma unroll
        for (int nt = 0; nt < 8; nt++) {
            float p0 = __expf(sacc[nt][0] - mn0);
            float p1 = __expf(sacc[nt][1] - mn0);
            float p2 = __expf(sacc[nt][2] - mn1);
            float p3 = __expf(sacc[nt][3] - mn1);
            rs0 += p0 + p1;
            rs1 += p2 + p3;
            af[nt >> 1][(nt & 1) * 2]     = packh2(p0, p1);
            af[nt >> 1][(nt & 1) * 2 + 1] = packh2(p2, p3);
        }
        #pragma unroll
        for (int o = 1; o <= 2; o <<= 1) {
            rs0 += __shfl_xor_sync(0xffffffffu, rs0, o);
            rs1 += __shfl_xor_sync(0xffffffffu, rs1, o);
        }
        l0 = l0 * sc0 + rs0;
        l1 = l1 * sc1 + rs1;
        #pragma unroll
        for (int nt = 0; nt < 8; nt++) {
            oacc[nt][0] *= sc0; oacc[nt][1] *= sc0;
            oacc[nt][2] *= sc1; oacc[nt][3] *= sc1;
        }

        // O += P @ V (V frags via ldmatrix.trans; 64 d-cols)
        uint32_t sV = sb + SV_OFF + buf * 64 * KHB;
        #pragma unroll
        for (int ks = 0; ks < 4; ks++) {
            #pragma unroll
            for (int np = 0; np < 4; np++) {
                uint32_t tmp[4];
                ldsm4t(tmp, sV + vOff + (uint32_t)(ks * 16 * 72 + np * 16) * 2);
                uint32_t vfa[2] = {tmp[0], tmp[1]};
                uint32_t vfb[2] = {tmp[2], tmp[3]};
                mma16(oacc[2*np],     af[ks], vfa);
                mma16(oacc[2*np + 1], af[ks], vfb);
            }
        }
    }

    float inv0 = 1.0f / l0;
    float inv1 = 1.0f / l1;
    #pragma unroll
    for (int nt = 0; nt < 8; nt++) {
        int d = nt * 8 + 2 * t;
        size_t o0 = ((size_t)b * SS + q0 + qr0) * DD + h * HD + d;
        size_t o1 = ((size_t)b * SS + q0 + qr0 + 8) * DD + h * HD + d;
        *(__half2*)(out + o0) = __floats2half2_rn(oacc[nt][0] * inv0, oacc[nt][1] * inv0);
        *(__half2*)(out + o1) = __floats2half2_rn(oacc[nt][2] * inv1, oacc[nt][3] * inv1);
    }
}

// ---------------- launcher ----------------
extern "C" void kernel_launch(void* const* d_in, const int* in_sizes, int n_in,
                              void* d_out, int out_size)
{
    const float*         inp   = (const float*)d_in[0];
    const unsigned char* mask  = (const unsigned char*)d_in[1];
    const int*           relm  = (const int*)d_in[2];
    const float*         qkv_w = (const float*)d_in[3];
    const float*         relA  = (const float*)d_in[4];
    const float*         o_w   = (const float*)d_in[5];
    const float*         w1    = (const float*)d_in[6];
    const float*         b1    = (const float*)d_in[7];
    const float*         w2    = (const float*)d_in[8];
    const float*         b2    = (const float*)d_in[9];
    const float*         ln1g  = (const float*)d_in[10];
    const float*         ln1b  = (const float*)d_in[11];
    const float*         ln2g  = (const float*)d_in[12];
    const float*         ln2b  = (const float*)d_in[13];
    float* out = (float*)d_out;

    __half *hxln, *hqkv, *hattn, *hh1, *hw;
    float *res1;
    unsigned char* relpack;
    cudaGetSymbolAddress((void**)&hxln,    g_hxln);
    cudaGetSymbolAddress((void**)&hqkv,    g_hqkv);
    cudaGetSymbolAddress((void**)&hattn,   g_hattn);
    cudaGetSymbolAddress((void**)&hh1,     g_hh1);
    cudaGetSymbolAddress((void**)&hw,      g_hw);
    cudaGetSymbolAddress((void**)&res1,    g_res1);
    cudaGetSymbolAddress((void**)&relpack, g_relpack);

    cudaFuncSetAttribute(gemm_h_kernel<4>, cudaFuncAttributeMaxDynamicSharedMemorySize, GEMM_SMEM_128);
    cudaFuncSetAttribute(gemm_h_kernel<2>, cudaFuncAttributeMaxDynamicSharedMemorySize, GEMM_SMEM_64);
    cudaFuncSetAttribute(flash_attn_kernel, cudaFuncAttributeMaxDynamicSharedMemorySize, FATTN_SMEM);

    const __half* qkv_wh = hw + W_QKV_OFF;
    const __half* o_wh   = hw + W_O_OFF;
    const __half* w1h    = hw + W_W1_OFF;
    const __half* w2h    = hw + W_W2_OFF;

    // 0a) convert all weights to half
    {
        int n0 = TD * DD / 4, n1 = DD * DD / 4, n2 = DFF * DD / 4, n3 = DD * DFF / 4;
        int ntot = n0 + n1 + n2 + n3;
        h_convert_kernel<<<(ntot + 255) / 256, 256>>>(
            (const float4*)qkv_w, n0, (const float4*)o_w, n1,
            (const float4*)w1, n2, (const float4*)w2, n3, (__half2*)hw);
    }
    // 0b) pack rel indices to u8
    pack_kernel<<<(BB * SS * SS + 255) / 256, 256>>>(relm, relpack, BB * SS * SS);

    // 1) LN1 -> half
    ln_kernel<<<MROWS, 256>>>(inp, ln1g, ln1b, hxln);

    // 2) QKV = xln @ qkv_w^T  -> half   (BM=128)
    gemm_h_kernel<4><<<dim3(TD / 128, MROWS / 128), 256, GEMM_SMEM_128>>>(
        hxln, qkv_wh, nullptr, nullptr, nullptr, hqkv, TD, DD, 0);

    // 3) flash attention -> half  (128 queries per CTA)
    flash_attn_kernel<<<dim3(SS / 128, HH, BB), 256, FATTN_SMEM>>>(
        hqkv, relpack, mask, relA, hattn);

    // 4) res1 = inp + attn @ o_w^T  -> fp32   (BM=64)
    gemm_h_kernel<2><<<dim3(DD / 128, MROWS / 64), 256, GEMM_SMEM_64>>>(
        hattn, o_wh, nullptr, inp, res1, nullptr, DD, DD, 0);

    // 5) LN2 -> half
    ln_kernel<<<MROWS, 256>>>(res1, ln2g, ln2b, hxln);

    // 6) h1 = relu(xln @ w1^T + b1)  -> half   (BM=128)
    gemm_h_kernel<4><<<dim3(DFF / 128, MROWS / 128), 256, GEMM_SMEM_128>>>(
        hxln, w1h, b1, nullptr, nullptr, hh1, DFF, DD, 1);

    // 7) out = res1 + h1 @ w2^T + b2  -> fp32   (BM=64)
    gemm_h_kernel<2><<<dim3(DD / 128, MROWS / 64), 256, GEMM_SMEM_64>>>(
        hh1, w2h, b2, res1, out, nullptr, DD, DFF, 0);
}

// round 16
// speedup vs baseline: 1.4257x; 1.4257x over previous
#include <cuda_runtime.h>
#include <cuda_fp16.h>
#include <math.h>
#include <cstdint>

// Problem constants
#define BB 2
#define SS 1024
#define DD 768
#define HH 12
#define HD 64
#define DFF 3072
#define TD 2304           // 3*D
#define MROWS (BB*SS)     // 2048

// weight scratch offsets (halfs)
#define W_QKV_OFF 0
#define W_O_OFF   (TD * DD)
#define W_W1_OFF  (W_O_OFF + DD * DD)
#define W_W2_OFF  (W_W1_OFF + DFF * DD)
#define W_TOTAL   (W_W2_OFF + DD * DFF)

// ---------------- scratch (__device__ globals; no allocation) ----------------
__device__ __half g_hxln[MROWS * DD];
__device__ __half g_hqkv[MROWS * TD];
__device__ __half g_hattn[MROWS * DD];
__device__ __half g_hh1[MROWS * DFF];
__device__ __half g_hw[W_TOTAL];
__device__ float  g_res1[MROWS * DD];
__device__ unsigned char g_relpack[BB * SS * SS];

// ================= helpers =================
__device__ __forceinline__ uint32_t smem_to_u32(const void* p) {
    uint32_t a;
    asm("{ .reg .u64 t; cvta.to.shared.u64 t, %1; cvt.u32.u64 %0, t; }" : "=r"(a) : "l"(p));
    return a;
}
__device__ __forceinline__ void cp16(uint32_t saddr, const void* gaddr) {
    asm volatile("cp.async.cg.shared.global [%0], [%1], 16;" :: "r"(saddr), "l"(gaddr) : "memory");
}
#define CP_COMMIT() asm volatile("cp.async.commit_group;" ::: "memory")
#define CP_WAIT(n)  asm volatile("cp.async.wait_group %0;" :: "n"(n) : "memory")

__device__ __forceinline__ void ldsm4(uint32_t* r, uint32_t a) {
    asm volatile("ldmatrix.sync.aligned.m8n8.x4.shared.b16 {%0,%1,%2,%3}, [%4];"
        : "=r"(r[0]), "=r"(r[1]), "=r"(r[2]), "=r"(r[3]) : "r"(a));
}
__device__ __forceinline__ void ldsm4t(uint32_t* r, uint32_t a) {
    asm volatile("ldmatrix.sync.aligned.m8n8.x4.trans.shared.b16 {%0,%1,%2,%3}, [%4];"
        : "=r"(r[0]), "=r"(r[1]), "=r"(r[2]), "=r"(r[3]) : "r"(a));
}
// D(16x8) += A(16x16) * B(16x8), f16 in, f32 accum
__device__ __forceinline__ void mma16(float* c, const uint32_t* a, const uint32_t* b) {
    asm volatile("mma.sync.aligned.m16n8k16.row.col.f32.f16.f16.f32 "
        "{%0,%1,%2,%3}, {%4,%5,%6,%7}, {%8,%9}, {%0,%1,%2,%3};"
        : "+f"(c[0]), "+f"(c[1]), "+f"(c[2]), "+f"(c[3])
        : "r"(a[0]), "r"(a[1]), "r"(a[2]), "r"(a[3]), "r"(b[0]), "r"(b[1]));
}

// ================= f16 mma GEMM: C[m][n] = sum_k A[m][k]*B[n][k] ================
// BM = MT*32 (MT=4 -> 128, MT=2 -> 64), BN=128, BK=64 halfs, 2 stages.
// 256 threads = 8 warps (2x4): warp tile (MT*16) x 32.
// smem rows: 72 halfs (144B) stride -> ldmatrix conflict-free.
template<int MT>
__global__ void __launch_bounds__(256) gemm_h_kernel(
    const __half* __restrict__ A, const __half* __restrict__ B,
    const float* __restrict__ bias, const float* __restrict__ resid,
    float* __restrict__ Cf, __half* __restrict__ Ch,
    int N, int K, int do_relu)
{
    constexpr int BM = MT * 32;
    constexpr int STAGE = (BM + 128) * 144;       // bytes per stage (A + B)
    extern __shared__ char smem[];
    uint32_t sb = smem_to_u32(smem);
    int tid = threadIdx.x;
    int warp = tid >> 5, lane = tid & 31;
    int g = lane >> 2, t = lane & 3;
    int q8 = lane >> 3, r8 = lane & 7;
    int wm = warp >> 2, wn = warp & 3;
    int row0 = blockIdx.y * BM, col0 = blockIdx.x * 128;
    int ktiles = K >> 6;

    const __half* gA = A + (size_t)row0 * K;
    const __half* gB = B + (size_t)col0 * K;

    float acc[MT][4][4];
    #pragma unroll
    for (int i = 0; i < MT; i++)
        #pragma unroll
        for (int j = 0; j < 4; j++)
            #pragma unroll
            for (int e = 0; e < 4; e++) acc[i][j][e] = 0.0f;

    // per stage: A = BM rows x 8 chunks of 16B, B = 128 rows x 8 chunks
    auto load_tile = [&](int kt, int buf) {
        uint32_t s0 = sb + buf * STAGE;
        const __half* a = gA + kt * 64;
        const __half* b = gB + kt * 64;
        #pragma unroll
        for (int j = 0; j < MT; j++) {
            int e = tid + j * 256;              // 0..BM*8-1
            int r = e >> 3, c = e & 7;
            cp16(s0 + (uint32_t)(r * 144 + c * 16), a + (size_t)r * K + c * 8);
        }
        uint32_t sB0 = s0 + (uint32_t)BM * 144;
        #pragma unroll
        for (int j = 0; j < 4; j++) {
            int e = tid + j * 256;              // 0..1023
            int r = e >> 3, c = e & 7;
            cp16(sB0 + (uint32_t)(r * 144 + c * 16), b + (size_t)r * K + c * 8);
        }
        CP_COMMIT();
    };

    load_tile(0, 0);

    uint32_t aOff = ((uint32_t)(wm * MT * 16 + (q8 & 1) * 8 + r8) * 72 + (q8 >> 1) * 8) * 2;
    uint32_t bOff = ((uint32_t)(wn * 32 + (q8 >> 1) * 8 + r8) * 72 + (q8 & 1) * 8) * 2;

    for (int kt = 0; kt < ktiles; kt++) {
        int buf = kt & 1;
        CP_WAIT(0);
        __syncthreads();
        if (kt + 1 < ktiles) load_tile(kt + 1, buf ^ 1);

        uint32_t sA = sb + buf * STAGE;
        uint32_t sB = sA + (uint32_t)BM * 144;

        #pragma unroll
        for (int ks = 0; ks < 4; ks++) {
            uint32_t af[MT][4];
            #pragma unroll
            for (int mt = 0; mt < MT; mt++)
                ldsm4(af[mt], sA + aOff + (uint32_t)(mt * 16 * 72 + ks * 16) * 2);
            uint32_t bf[4][2];
            #pragma unroll
            for (int np = 0; np < 2; np++) {
                uint32_t tmp[4];
                ldsm4(tmp, sB + bOff + (uint32_t)(np * 16 * 72 + ks * 16) * 2);
                bf[2*np][0] = tmp[0]; bf[2*np][1] = tmp[1];
                bf[2*np+1][0] = tmp[2]; bf[2*np+1][1] = tmp[3];
            }
            #pragma unroll
            for (int mt = 0; mt < MT; mt++)
                #pragma unroll
                for (int nt = 0; nt < 4; nt++)
                    mma16(acc[mt][nt], af[mt], bf[nt]);
        }
    }
    __syncthreads();

    // epilogue: stage fp32 through smem, fused coalesced store
    float* eb = (float*)smem;
    #pragma unroll
    for (int mt = 0; mt < MT; mt++) {
        int r0 = wm * MT * 16 + mt * 16 + g;
        #pragma unroll
        for (int nt = 0; nt < 4; nt++) {
            int c0 = wn * 32 + nt * 8 + 2 * t;
            eb[r0 * 132 + c0]           = acc[mt][nt][0];
            eb[r0 * 132 + c0 + 1]       = acc[mt][nt][1];
            eb[(r0 + 8) * 132 + c0]     = acc[mt][nt][2];
            eb[(r0 + 8) * 132 + c0 + 1] = acc[mt][nt][3];
        }
    }
    __syncthreads();

    int c = tid & 127;
    int rs = tid >> 7;
    float bv = bias ? bias[col0 + c] : 0.0f;
    for (int r = rs; r < BM; r += 2) {
        float v = eb[r * 132 + c] + bv;
        size_t off = (size_t)(row0 + r) * N + col0 + c;
        if (resid) v += resid[off];
        if (do_relu) v = fmaxf(v, 0.0f);
        if (Ch) Ch[off] = __float2half(v);
        else    Cf[off] = v;
    }
}

#define GEMM_SMEM_128 73728    // 2 * (128+128)*144
#define GEMM_SMEM_64  55296    // 2 * (64+128)*144

// ---------------- LayerNorm: fp32 in, half out ----------------
__global__ void ln_kernel(const float* __restrict__ x,
                          const float* __restrict__ g,
                          const float* __restrict__ b,
                          __half* __restrict__ y)
{
    __shared__ float s1[256], s2[256];
    int row = blockIdx.x;
    const float* xr = x + (size_t)row * DD;
    __half* yr = y + (size_t)row * DD;
    int tid = threadIdx.x;

    float v0 = xr[tid], v1 = xr[tid + 256], v2 = xr[tid + 512];
    float sum = v0 + v1 + v2;
    float sq  = v0*v0 + v1*v1 + v2*v2;
    s1[tid] = sum; s2[tid] = sq;
    __syncthreads();
    for (int o = 128; o > 0; o >>= 1) {
        if (tid < o) { s1[tid] += s1[tid+o]; s2[tid] += s2[tid+o]; }
        __syncthreads();
    }
    float mean = s1[0] * (1.0f / DD);
    float var  = s2[0] * (1.0f / DD) - mean * mean;
    float inv  = rsqrtf(var + 1e-5f);
    yr[tid]       = __float2half((v0 - mean) * inv * g[tid]       + b[tid]);
    yr[tid + 256] = __float2half((v1 - mean) * inv * g[tid + 256] + b[tid + 256]);
    yr[tid + 512] = __float2half((v2 - mean) * inv * g[tid + 512] + b[tid + 512]);
}

// ---------------- prep ----------------
__global__ void pack_kernel(const int* __restrict__ relm, unsigned char* __restrict__ out, int n)
{
    int i = blockIdx.x * 256 + threadIdx.x;
    if (i < n) out[i] = (unsigned char)(relm[i] + 1);
}

__global__ void h_convert_kernel(const float4* __restrict__ s0, int n0,
                                 const float4* __restrict__ s1, int n1,
                                 const float4* __restrict__ s2, int n2,
                                 const float4* __restrict__ s3, int n3,
                                 __half2* __restrict__ dst)
{
    int i = blockIdx.x * 256 + threadIdx.x;
    const float4* s;
    int j = i;
    if (j < n0) s = s0;
    else { j -= n0;
        if (j < n1) { s = s1; }
        else { j -= n1;
            if (j < n2) { s = s2; }
            else { j -= n2; if (j >= n3) return; s = s3; }
        }
    }
    float4 v = s[j];
    dst[2*i]   = __floats2half2_rn(v.x, v.y);
    dst[2*i+1] = __floats2half2_rn(v.z, v.w);
}

// ================= fp16 flash attention (ldmatrix + m16n8k16) =================
// CTA: 64 queries x head x batch. 256 threads = 8 warps: 4(q) x 2(k/d).
// K/V/P/Q smem rows: 72 halfs (144B) stride -> ldmatrix conflict-free.
#define KHB 144                    // bytes per smem row
#define SK_OFF 0                   // K: 2 x 64 x 144 = 18432
#define SV_OFF 18432               // V: 18432
#define SP_OFF 36864               // P / Q staging: 9216
#define RR_OFF 46080               // float area from here
#define M_OFF  (RR_OFF + 768)
#define L_OFF  (M_OFF + 256)
#define SC_OFF (L_OFF + 256)
#define PM_OFF (SC_OFF + 256)
#define PS_OFF (PM_OFF + 512)
#define FATTN_SMEM (PS_OFF + 512)  // 48640

__global__ void __launch_bounds__(256, 2) flash_attn_kernel(
    const __half* __restrict__ qkv,
    const unsigned char* __restrict__ relpack,
    const unsigned char* __restrict__ mask,
    const float* __restrict__ relA,
    __half* __restrict__ out)
{
    extern __shared__ char smem[];
    uint32_t sb = smem_to_u32(smem);
    __half* Ph  = (__half*)(smem + SP_OFF);
    float* rr  = (float*)(smem + RR_OFF);
    float* m_s = (float*)(smem + M_OFF);
    float* l_s = (float*)(smem + L_OFF);
    float* sc_s= (float*)(smem + SC_OFF);
    float* pm  = (float*)(smem + PM_OFF);
    float* ps  = (float*)(smem + PS_OFF);

    int tid = threadIdx.x;
    int warp = tid >> 5, lane = tid & 31;
    int g = lane >> 2, t = lane & 3;
    int q8 = lane >> 3, r8 = lane & 7;
    int wq = warp & 3, wk = warp >> 2;
    int q0 = blockIdx.x * 64;
    int h  = blockIdx.y;
    int b  = blockIdx.z;
    const __half* base = qkv + (size_t)b * SS * TD;
    const unsigned char* relrow = relpack + ((size_t)b * SS + q0) * SS;
    const unsigned char* maskp = mask + b * SS;

    // stage Q*0.125 into P buffer (exact scale); init stats
    for (int i = tid; i < 64 * 32; i += 256) {
        int q = i >> 5, d2 = i & 31;
        const __half2 v = *(const __half2*)(base + (size_t)(q0 + q) * TD + h * HD + d2 * 2);
        float2 f = __half22float2(v);
        *(__half2*)(Ph + q * 72 + d2 * 2) = __floats2half2_rn(f.x * 0.125f, f.y * 0.125f);
    }
    if (tid < 64) { m_s[tid] = -1e30f; l_s[tid] = 0.0f; }
    __syncthreads();

    // rel projections rr[q][c] (from scaled Q; scale folds into scores)
    if (tid < 192) {
        int q = tid / 3, c = tid % 3;
        float s = 0.0f;
        #pragma unroll
        for (int d = 0; d < HD; d++) s += __half2float(Ph[q * 72 + d]) * relA[c * HD + d];
        rr[q * 3 + c] = s;
    }
    __syncthreads();

    // Q fragments (held whole kernel): 4 ksteps of k16
    uint32_t qf[4][4];
    {
        uint32_t qOff = sb + SP_OFF + ((uint32_t)(wq * 16 + (q8 & 1) * 8 + r8) * 72 + (q8 >> 1) * 8) * 2;
        #pragma unroll
        for (int ks = 0; ks < 4; ks++)
            ldsm4(qf[ks], qOff + (uint32_t)(ks * 16) * 2);
    }
    __syncthreads();    // P buffer free for reuse

    // K+V loader: 64 rows x 64 halfs each (8KB each)
    auto load_tile = [&](int kt, int buf) {
        uint32_t sK = sb + SK_OFF + buf * 64 * KHB;
        uint32_t sV = sb + SV_OFF + buf * 64 * KHB;
        const __half* srcK = base + (size_t)kt * 64 * TD + DD + h * HD;
        const __half* srcV = base + (size_t)kt * 64 * TD + 2 * DD + h * HD;
        #pragma unroll
        for (int j = 0; j < 2; j++) {
            int e = tid + j * 256;          // 0..511
            int r = e >> 3, c = e & 7;      // 64 rows x 8 chunks of 16B
            cp16(sK + (uint32_t)(r * KHB + c * 16), srcK + (size_t)r * TD + c * 8);
            cp16(sV + (uint32_t)(r * KHB + c * 16), srcV + (size_t)r * TD + c * 8);
        }
        CP_COMMIT();
    };

    float oacc[4][4];
    #pragma unroll
    for (int nt = 0; nt < 4; nt++)
        #pragma unroll
        for (int e = 0; e < 4; e++) oacc[nt][e] = 0.0f;

    load_tile(0, 0);

    // per-thread ldmatrix offsets
    uint32_t kOff = ((uint32_t)(wk * 32 + (q8 >> 1) * 8 + r8) * 72 + (q8 & 1) * 8) * 2; // K (non-trans)
    uint32_t pOff = ((uint32_t)(wq * 16 + (q8 & 1) * 8 + r8) * 72 + (q8 >> 1) * 8) * 2; // P (A frags)
    uint32_t vOff = ((uint32_t)((q8 & 1) * 8 + r8) * 72 + wk * 32 + (q8 >> 1) * 8) * 2; // V (trans)

    for (int kt = 0; kt < 16; kt++) {
        int buf = kt & 1;
        CP_WAIT(0);
        __syncthreads();
        if (kt + 1 < 16) load_tile(kt + 1, buf ^ 1);

        // prefetch rel idx + mask bytes
        unsigned idxv[4][4];
        unsigned mv[4][2];
        #pragma unroll
        for (int nt = 0; nt < 4; nt++) {
            #pragma unroll
            for (int e = 0; e < 4; e++) {
                int q  = wq * 16 + g + 8 * (e >> 1);
                int gk = kt * 64 + wk * 32 + nt * 8 + 2 * t + (e & 1);
                idxv[nt][e] = relrow[(size_t)q * SS + gk];
            }
            int gk0 = kt * 64 + wk * 32 + nt * 8 + 2 * t;
            mv[nt][0] = maskp[gk0];
            mv[nt][1] = maskp[gk0 + 1];
        }

        // S = Qs K^T
        float sacc[4][4];
        #pragma unroll
        for (int nt = 0; nt < 4; nt++)
            #pragma unroll
            for (int e = 0; e < 4; e++) sacc[nt][e] = 0.0f;
        uint32_t sK = sb + SK_OFF + buf * 64 * KHB;
        #pragma unroll
        for (int ks = 0; ks < 4; ks++) {
            uint32_t bf[4][2];
            #pragma unroll
            for (int np = 0; np < 2; np++) {
                uint32_t tmp[4];
                ldsm4(tmp, sK + kOff + (uint32_t)(np * 16 * 72 + ks * 16) * 2);
                bf[2*np][0] = tmp[0]; bf[2*np][1] = tmp[1];
                bf[2*np+1][0] = tmp[2]; bf[2*np+1][1] = tmp[3];
            }
            #pragma unroll
            for (int nt = 0; nt < 4; nt++)
                mma16(sacc[nt], qf[ks], bf[nt]);
        }

        // epilogue: +rel, mask; partial row max
        float rowmax[2] = {-1e30f, -1e30f};
        #pragma unroll
        for (int nt = 0; nt < 4; nt++) {
            #pragma unroll
            for (int e = 0; e < 4; e++) {
                int qr = wq * 16 + g + 8 * (e >> 1);
                float s = sacc[nt][e] + rr[qr * 3 + idxv[nt][e]];
                if (mv[nt][e & 1]) s = -1e30f;
                sacc[nt][e] = s;
                rowmax[e >> 1] = fmaxf(rowmax[e >> 1], s);
            }
        }
        #pragma unroll
        for (int o = 1; o <= 2; o <<= 1) {
            rowmax[0] = fmaxf(rowmax[0], __shfl_xor_sync(0xffffffffu, rowmax[0], o));
            rowmax[1] = fmaxf(rowmax[1], __shfl_xor_sync(0xffffffffu, rowmax[1], o));
        }
        if (t == 0) {
            pm[wk * 64 + wq * 16 + g]     = rowmax[0];
            pm[wk * 64 + wq * 16 + 8 + g] = rowmax[1];
        }
        __syncthreads();

        if (tid < 64) {
            float mo = m_s[tid];
            float mn = fmaxf(mo, fmaxf(pm[tid], pm[64 + tid]));
            m_s[tid] = mn;
            sc_s[tid] = __expf(mo - mn);
        }
        __syncthreads();

        // P = exp(s - m) -> half; partial sums; rescale O
        float rowsum[2] = {0.0f, 0.0f};
        float mrow0 = m_s[wq * 16 + g], mrow1 = m_s[wq * 16 + 8 + g];
        #pragma unroll
        for (int nt = 0; nt < 4; nt++) {
            float p0 = __expf(sacc[nt][0] - mrow0);
            float p1 = __expf(sacc[nt][1] - mrow0);
            float p2 = __expf(sacc[nt][2] - mrow1);
            float p3 = __expf(sacc[nt][3] - mrow1);
            rowsum[0] += p0 + p1;
            rowsum[1] += p2 + p3;
            int kc = wk * 32 + nt * 8 + 2 * t;
            *(__half2*)(Ph + (wq * 16 + g) * 72 + kc)     = __floats2half2_rn(p0, p1);
            *(__half2*)(Ph + (wq * 16 + 8 + g) * 72 + kc) = __floats2half2_rn(p2, p3);
        }
        #pragma unroll
        for (int o = 1; o <= 2; o <<= 1) {
            rowsum[0] += __shfl_xor_sync(0xffffffffu, rowsum[0], o);
            rowsum[1] += __shfl_xor_sync(0xffffffffu, rowsum[1], o);
        }
        if (t == 0) {
            ps[wk * 64 + wq * 16 + g]     = rowsum[0];
            ps[wk * 64 + wq * 16 + 8 + g] = rowsum[1];
        }
        float s0 = sc_s[wq * 16 + g], s1 = sc_s[wq * 16 + 8 + g];
        #pragma unroll
        for (int nt = 0; nt < 4; nt++) {
            oacc[nt][0] *= s0; oacc[nt][1] *= s0;
            oacc[nt][2] *= s1; oacc[nt][3] *= s1;
        }
        __syncthreads();

        if (tid < 64)
            l_s[tid] = l_s[tid] * sc_s[tid] + ps[tid] + ps[64 + tid];

        // O += P @ V (V frags via ldmatrix.trans)
        uint32_t sV = sb + SV_OFF + buf * 64 * KHB;
        #pragma unroll
        for (int ks = 0; ks < 4; ks++) {
            uint32_t af[4];
            ldsm4(af, sb + SP_OFF + pOff + (uint32_t)(ks * 16) * 2);
            uint32_t vf[4][2];
            #pragma unroll
            for (int np = 0; np < 2; np++) {
                uint32_t tmp[4];
                ldsm4t(tmp, sV + vOff + (uint32_t)(ks * 16 * 72 + np * 16) * 2);
                vf[2*np][0] = tmp[0]; vf[2*np][1] = tmp[1];
                vf[2*np+1][0] = tmp[2]; vf[2*np+1][1] = tmp[3];
            }
            #pragma unroll
            for (int nt = 0; nt < 4; nt++)
                mma16(oacc[nt], af, vf[nt]);
        }
    }
    __syncthreads();

    float inv0 = 1.0f / l_s[wq * 16 + g];
    float inv1 = 1.0f / l_s[wq * 16 + 8 + g];
    #pragma unroll
    for (int nt = 0; nt < 4; nt++) {
        int d = wk * 32 + nt * 8 + 2 * t;
        size_t o0 = ((size_t)b * SS + q0 + wq * 16 + g) * DD + h * HD + d;
        size_t o1 = ((size_t)b * SS + q0 + wq * 16 + 8 + g) * DD + h * HD + d;
        *(__half2*)(out + o0) = __floats2half2_rn(oacc[nt][0] * inv0, oacc[nt][1] * inv0);
        *(__half2*)(out + o1) = __floats2half2_rn(oacc[nt][2] * inv1, oacc[nt][3] * inv1);
    }
}

// ---------------- launcher ----------------
extern "C" void kernel_launch(void* const* d_in, const int* in_sizes, int n_in,
                              void* d_out, int out_size)
{
    const float*         inp   = (const float*)d_in[0];
    const unsigned char* mask  = (const unsigned char*)d_in[1];
    const int*           relm  = (const int*)d_in[2];
    const float*         qkv_w = (const float*)d_in[3];
    const float*         relA  = (const float*)d_in[4];
    const float*         o_w   = (const float*)d_in[5];
    const float*         w1    = (const float*)d_in[6];
    const float*         b1    = (const float*)d_in[7];
    const float*         w2    = (const float*)d_in[8];
    const float*         b2    = (const float*)d_in[9];
    const float*         ln1g  = (const float*)d_in[10];
    const float*         ln1b  = (const float*)d_in[11];
    const float*         ln2g  = (const float*)d_in[12];
    const float*         ln2b  = (const float*)d_in[13];
    float* out = (float*)d_out;

    __half *hxln, *hqkv, *hattn, *hh1, *hw;
    float *res1;
    unsigned char* relpack;
    cudaGetSymbolAddress((void**)&hxln,    g_hxln);
    cudaGetSymbolAddress((void**)&hqkv,    g_hqkv);
    cudaGetSymbolAddress((void**)&hattn,   g_hattn);
    cudaGetSymbolAddress((void**)&hh1,     g_hh1);
    cudaGetSymbolAddress((void**)&hw,      g_hw);
    cudaGetSymbolAddress((void**)&res1,    g_res1);
    cudaGetSymbolAddress((void**)&relpack, g_relpack);

    cudaFuncSetAttribute(gemm_h_kernel<4>, cudaFuncAttributeMaxDynamicSharedMemorySize, GEMM_SMEM_128);
    cudaFuncSetAttribute(gemm_h_kernel<2>, cudaFuncAttributeMaxDynamicSharedMemorySize, GEMM_SMEM_64);
    cudaFuncSetAttribute(flash_attn_kernel, cudaFuncAttributeMaxDynamicSharedMemorySize, FATTN_SMEM);

    const __half* qkv_wh = hw + W_QKV_OFF;
    const __half* o_wh   = hw + W_O_OFF;
    const __half* w1h    = hw + W_W1_OFF;
    const __half* w2h    = hw + W_W2_OFF;

    // 0a) convert all weights to half
    {
        int n0 = TD * DD / 4, n1 = DD * DD / 4, n2 = DFF * DD / 4, n3 = DD * DFF / 4;
        int ntot = n0 + n1 + n2 + n3;
        h_convert_kernel<<<(ntot + 255) / 256, 256>>>(
            (const float4*)qkv_w, n0, (const float4*)o_w, n1,
            (const float4*)w1, n2, (const float4*)w2, n3, (__half2*)hw);
    }
    // 0b) pack rel indices to u8
    pack_kernel<<<(BB * SS * SS + 255) / 256, 256>>>(relm, relpack, BB * SS * SS);

    // 1) LN1 -> half
    ln_kernel<<<MROWS, 256>>>(inp, ln1g, ln1b, hxln);

    // 2) QKV = xln @ qkv_w^T  -> half   (BM=128)
    gemm_h_kernel<4><<<dim3(TD / 128, MROWS / 128), 256, GEMM_SMEM_128>>>(
        hxln, qkv_wh, nullptr, nullptr, nullptr, hqkv, TD, DD, 0);

    // 3) flash attention -> half
    flash_attn_kernel<<<dim3(SS / 64, HH, BB), 256, FATTN_SMEM>>>(
        hqkv, relpack, mask, relA, hattn);

    // 4) res1 = inp + attn @ o_w^T  -> fp32   (BM=64: grid 6x32=192)
    gemm_h_kernel<2><<<dim3(DD / 128, MROWS / 64), 256, GEMM_SMEM_64>>>(
        hattn, o_wh, nullptr, inp, res1, nullptr, DD, DD, 0);

    // 5) LN2 -> half
    ln_kernel<<<MROWS, 256>>>(res1, ln2g, ln2b, hxln);

    // 6) h1 = relu(xln @ w1^T + b1)  -> half   (BM=128)
    gemm_h_kernel<4><<<dim3(DFF / 128, MROWS / 128), 256, GEMM_SMEM_128>>>(
        hxln, w1h, b1, nullptr, nullptr, hh1, DFF, DD, 1);

    // 7) out = res1 + h1 @ w2^T + b2  -> fp32   (BM=64: grid 6x32=192)
    gemm_h_kernel<2><<<dim3(DD / 128, MROWS / 64), 256, GEMM_SMEM_64>>>(
        hh1, w2h, b2, res1, out, nullptr, DD, DFF, 0);
}